// round 4
// baseline (speedup 1.0000x reference)
#include <cuda_runtime.h>
#include <stdint.h>
#include <math.h>

#define NTHREADS 512
#define NB 18
#define NPAIR 1500
#define NBLOCKS 640

#define BPW 260            // bins row pitch in words (1040 B)
#define APW 260            // amp row pitch in words
#define DPW 57             // Dsm row pitch in floats

// word offsets into dynamic smem
#define OFF_BINS_W 0                  // 31*260  = 8060
#define OFF_HI_W   8060               // 56*260  = 14560
#define OFF_LO_W   22620              // 14560
#define OFF_DSM_W  37180              // 144*57  = 8208
#define OFF_CUT_W  45388              // 20
#define SMEM_WORDS 45408              // 181,632 bytes

__device__ float g_mi[(size_t)NBLOCKS * NPAIR];

#define IMMA(D, A0, A1, A2, A3, B0, B1) \
    asm volatile("mma.sync.aligned.m16n8k32.row.col.s32.u8.u8.s32 " \
        "{%0,%1,%2,%3}, {%4,%5,%6,%7}, {%8,%9}, {%0,%1,%2,%3};" \
        : "+r"((D)[0]), "+r"((D)[1]), "+r"((D)[2]), "+r"((D)[3]) \
        : "r"(A0), "r"(A1), "r"(A2), "r"(A3), "r"(B0), "r"(B1))

__global__ void __launch_bounds__(NTHREADS)
mi_imma(const float* __restrict__ pha, const float* __restrict__ amp,
        const float* __restrict__ cut_g)
{
    extern __shared__ uint32_t smw[];
    uint32_t* bins32 = smw + OFF_BINS_W;
    uint32_t* hi32   = smw + OFF_HI_W;
    uint32_t* lo32   = smw + OFF_LO_W;
    float*    Dsm    = (float*)(smw + OFF_DSM_W);
    float*    cut    = (float*)(smw + OFF_CUT_W);

    const int tid = threadIdx.x;
    const int w = tid >> 5, l = tid & 31;
    const int bc = blockIdx.x / 20, s = blockIdx.x % 20;
    const float* pha_base = pha + ((size_t)bc * 600 + s) * 1024;
    const float* amp_base = amp + ((size_t)bc * 1000 + s) * 1024;

    if (tid < 19) cut[tid] = cut_g[tid];
    // bins padding row p=30: 0xFF never matches any k in 0..17
    for (int i = tid; i < BPW; i += NTHREADS) bins32[30 * BPW + i] = 0xFFFFFFFFu;
    __syncthreads();
    const float c0 = cut[0];
    const float invs = 18.0f / (cut[18] - cut[0]);

    // ---- phase 1a: bins (exact searchsorted via affine guess + fixups) ----
    for (int idx = tid; idx < 30 * 256; idx += NTHREADS) {
        const int p = idx >> 8, tw = idx & 255;
        const float4 v = *(const float4*)(pha_base + p * 20480 + tw * 4);
        const float vv[4] = {v.x, v.y, v.z, v.w};
        uint32_t word = 0;
        #pragma unroll
        for (int j = 0; j < 4; ++j) {
            const float x = vv[j];
            int k = (int)floorf((x - c0) * invs);
            k = k < 0 ? 0 : (k > 17 ? 17 : k);
            k += (k < 17 && cut[k + 1] < x);
            k += (k < 17 && cut[k + 1] < x);
            k -= (k > 0 && !(cut[k] < x));
            k -= (k > 0 && !(cut[k] < x));
            word |= (uint32_t)k << (8 * j);
        }
        bins32[p * BPW + tw] = word;
    }
    // ---- phase 1b: amp -> u16 fixed point, split hi/lo byte planes ----
    for (int idx = tid; idx < 50 * 256; idx += NTHREADS) {
        const int a = idx >> 8, tw = idx & 255;
        const float4 v = *(const float4*)(amp_base + a * 20480 + tw * 4);
        const uint32_t q0 = __float2uint_rn(v.x * 65535.0f);
        const uint32_t q1 = __float2uint_rn(v.y * 65535.0f);
        const uint32_t q2 = __float2uint_rn(v.z * 65535.0f);
        const uint32_t q3 = __float2uint_rn(v.w * 65535.0f);
        hi32[a * APW + tw] = (q0 >> 8) | (((q1 >> 8) & 255u) << 8)
                           | (((q2 >> 8) & 255u) << 16) | ((q3 >> 8) << 24);
        lo32[a * APW + tw] = (q0 & 255u) | ((q1 & 255u) << 8)
                           | ((q2 & 255u) << 16) | ((q3 & 255u) << 24);
    }
    // a=50: constant 65535 -> D col 50 = 65535 * counts; a=51..55: zero pad
    for (int idx = tid; idx < 6 * 256; idx += NTHREADS) {
        const int a = 50 + (idx >> 8), tw = idx & 255;
        const uint32_t v = (a == 50) ? 0xFFFFFFFFu : 0u;
        hi32[a * APW + tw] = v;
        lo32[a * APW + tw] = v;
    }
    __syncthreads();

    const float eps = 1e-9f;
    const float INVQ = 1.0f / 65535.0f;
    const float LOG18 = 2.8903717578961645f;

    // ---- phase 2: 4 passes of 8 p-groups (144 rows = 9 m16-tiles) ----
    #pragma unroll 1
    for (int pass = 0; pass < 4; ++pass) {
        const int ntiles = (pass < 3) ? 9 : 7;   // pass 3: 108 rows -> 7 tiles
        if (w < ntiles) {
            int d[7][8];
            #pragma unroll
            for (int nt = 0; nt < 7; ++nt)
                #pragma unroll
                for (int j = 0; j < 8; ++j) d[nt][j] = 0;

            const int g0 = pass * 144 + w * 16 + (l >> 2);
            const int g1 = g0 + 8;
            const int p0 = g0 / 18, p1 = g1 / 18;
            const uint32_t k0s = (uint32_t)(g0 % 18) * 0x01010101u;
            const uint32_t k1s = (uint32_t)(g1 % 18) * 0x01010101u;
            const uint32_t* bp0 = bins32 + p0 * BPW + (l & 3);
            const uint32_t* bp1 = bins32 + p1 * BPW + (l & 3);
            const uint32_t* hb = hi32 + (l >> 2) * APW + (l & 3);
            const uint32_t* lb = lo32 + (l >> 2) * APW + (l & 3);

            #pragma unroll 1
            for (int ks = 0; ks < 32; ++ks) {
                const int tw0 = ks * 8;
                const uint32_t a0 = __vcmpeq4(bp0[tw0],     k0s) & 0x01010101u;
                const uint32_t a1 = __vcmpeq4(bp1[tw0],     k1s) & 0x01010101u;
                const uint32_t a2 = __vcmpeq4(bp0[tw0 + 4], k0s) & 0x01010101u;
                const uint32_t a3 = __vcmpeq4(bp1[tw0 + 4], k1s) & 0x01010101u;
                #pragma unroll
                for (int nt = 0; nt < 7; ++nt) {
                    const int boff = nt * 8 * APW + tw0;
                    const uint32_t bh0 = hb[boff], bh1 = hb[boff + 4];
                    const uint32_t bl0 = lb[boff], bl1 = lb[boff + 4];
                    IMMA(d[nt],     a0, a1, a2, a3, bh0, bh1);
                    IMMA(d[nt] + 4, a0, a1, a2, a3, bl0, bl1);
                }
            }
            // writeback combined = 256*hi + lo (exact int) as f32
            #pragma unroll
            for (int nt = 0; nt < 7; ++nt)
                #pragma unroll
                for (int j = 0; j < 4; ++j) {
                    const int comb = d[nt][j] * 256 + d[nt][4 + j];
                    const int lr = w * 16 + (l >> 2) + ((j >> 1) << 3);
                    const int col = nt * 8 + ((l & 3) << 1) + (j & 1);
                    Dsm[lr * DPW + col] = (float)comb;
                }
        }
        __syncthreads();

        // ---- epilogue for this pass's p-groups ----
        const int np = (pass < 3) ? 8 : 6;
        for (int pr = tid; pr < np * 50; pr += NTHREADS) {
            const int pl = pr / 50, a = pr % 50;
            const float* row = Dsm + pl * 18 * DPW;
            float m[NB];
            float ss = 0.0f;
            #pragma unroll
            for (int k = 0; k < NB; ++k) {
                const float cnt = row[k * DPW + 50] * INVQ;
                const float mm = (row[k * DPW + a] * INVQ) / (cnt + eps);
                m[k] = mm;
                ss += mm;
            }
            const float inv = 1.0f / (ss + eps);
            float ent = 0.0f;
            #pragma unroll
            for (int k = 0; k < NB; ++k) {
                const float p = m[k] * inv;
                ent += p * logf(p + eps);
            }
            const int pg = pass * 8 + pl;
            g_mi[(size_t)blockIdx.x * NPAIR + pg * 50 + a] = (LOG18 + ent) * (1.0f / LOG18);
        }
        __syncthreads();
    }
}

__global__ void reduce_kernel(float* __restrict__ out)
{
    const int o = blockIdx.x * 256 + threadIdx.x;
    if (o >= 48000) return;
    const int bc = o / 1500, rem = o % 1500;
    float sum = 0.0f;
    #pragma unroll
    for (int s = 0; s < 20; ++s)
        sum += g_mi[(size_t)(bc * 20 + s) * NPAIR + rem];
    out[o] = sum * 0.05f;
}

extern "C" void kernel_launch(void* const* d_in, const int* in_sizes, int n_in,
                              void* d_out, int out_size)
{
    const float* pha = (const float*)d_in[0];
    const float* amp = (const float*)d_in[1];
    const float* cut = (const float*)d_in[2];
    cudaFuncSetAttribute(mi_imma, cudaFuncAttributeMaxDynamicSharedMemorySize,
                         SMEM_WORDS * 4);
    mi_imma<<<NBLOCKS, NTHREADS, SMEM_WORDS * 4>>>(pha, amp, cut);
    reduce_kernel<<<(48000 + 255) / 256, 256>>>((float*)d_out);
}

// round 5
// speedup vs baseline: 1.3044x; 1.3044x over previous
#include <cuda_runtime.h>
#include <stdint.h>
#include <math.h>

#define NTHREADS 512
#define NB 18
#define NPAIR 1500
#define NBLOCKS 640
#define TC 256
#define NCH 4
#define APITCH 52       // ampT row pitch (f32 words)
#define DPITCH 52       // Dsm row pitch
#define SPITCH 288      // sorted-idx row capacity (u16), >= 256 + 18 pad

// word offsets into dynamic smem
#define OFF_DSM   0         // 540*52        = 28080
#define OFF_AMPT  28080     // 257*52        = 13364 (row 256 = zero pad row)
#define OFF_SIDX  41444     // 30*288 u16    =  4320 words
#define OFF_BIN   45764     // 30*256 u8     =  1920 words
#define OFF_HIST  47684     // 30*18         =   540
#define OFF_PREF  48224     // 30*19         =   570
#define OFF_OFS   48794     //               =   540
#define OFF_CNT   49334     //               =   540
#define OFF_CUT   49874     //               =    20
#define SMEM_WORDS 49894    // 199,576 bytes

__device__ float g_mi[(size_t)NBLOCKS * NPAIR];

__global__ void __launch_bounds__(NTHREADS)
mi_sorted(const float* __restrict__ pha, const float* __restrict__ amp,
          const float* __restrict__ cut_g)
{
    extern __shared__ uint32_t smw[];
    float*     Dsm  = (float*)(smw + OFF_DSM);
    float*     ampT = (float*)(smw + OFF_AMPT);
    uint16_t*  sIdx = (uint16_t*)(smw + OFF_SIDX);
    uint8_t*   binT = (uint8_t*)(smw + OFF_BIN);
    uint32_t*  hist = smw + OFF_HIST;
    uint32_t*  pref = smw + OFF_PREF;
    uint32_t*  ofs  = smw + OFF_OFS;
    uint32_t*  cntT = smw + OFF_CNT;
    float*     cut  = (float*)(smw + OFF_CUT);

    const int tid = threadIdx.x;
    const int w = tid >> 5, l = tid & 31;
    const int bc = blockIdx.x / 20, s = blockIdx.x % 20;
    const float* pha_base = pha + ((size_t)bc * 600 + s) * 1024;
    const float* amp_base = amp + ((size_t)bc * 1000 + s) * 1024;

    for (int i = tid; i < 540 * DPITCH; i += NTHREADS) Dsm[i] = 0.0f;
    for (int i = tid; i < 540; i += NTHREADS) cntT[i] = 0u;
    if (tid < APITCH) ampT[256 * APITCH + tid] = 0.0f;   // zero pad row
    if (tid < 19) cut[tid] = cut_g[tid];
    __syncthreads();

    const float c0 = cut[0];
    const float invs = 18.0f / (cut[18] - cut[0]);

    for (int c = 0; c < NCH; ++c) {
        const int t0 = c * TC;
        __syncthreads();   // previous chunk's accumulate done before refilling
        for (int i = tid; i < 540; i += NTHREADS) hist[i] = 0u;
        for (int i = tid; i < 30 * SPITCH / 2; i += NTHREADS)
            ((uint32_t*)sIdx)[i] = 0x01000100u;   // pad idx = 256 (zero row)
        __syncthreads();

        // ---- binning (exact searchsorted via affine guess + fixups) + histogram ----
        for (int idx = tid; idx < 30 * TC; idx += NTHREADS) {
            const int p = idx >> 8, tt = idx & 255;
            const float x = pha_base[p * 20480 + t0 + tt];
            int k = (int)floorf((x - c0) * invs);
            k = k < 0 ? 0 : (k > 17 ? 17 : k);
            k += (k < 17 && cut[k + 1] < x);
            k += (k < 17 && cut[k + 1] < x);
            k -= (k > 0 && !(cut[k] < x));
            k -= (k > 0 && !(cut[k] < x));
            binT[idx] = (uint8_t)k;
            atomicAdd(&hist[p * NB + k], 1u);
        }
        // ---- stage amp transposed: ampT[t][a] (lanes differ in a -> conflict-free STS) ----
        for (int idx = tid; idx < 64 * TC; idx += NTHREADS) {
            const int a = idx & 63, tt = idx >> 6;
            if (a < 50) ampT[tt * APITCH + a] = amp_base[a * 20480 + t0 + tt];
        }
        __syncthreads();

        // ---- prefix (segments padded to even start/len) + counts total ----
        if (tid < 30) {
            uint32_t run = 0;
            #pragma unroll
            for (int k = 0; k < NB; ++k) {
                pref[tid * 19 + k] = run;
                ofs[tid * NB + k] = run;
                run += (hist[tid * NB + k] + 1u) & ~1u;
            }
            pref[tid * 19 + NB] = run;
        }
        for (int i = tid; i < 540; i += NTHREADS) cntT[i] += hist[i];
        __syncthreads();

        // ---- scatter sorted t-indices ----
        for (int idx = tid; idx < 30 * TC; idx += NTHREADS) {
            const int p = idx >> 8, tt = idx & 255;
            const uint32_t pos = atomicAdd(&ofs[p * NB + (int)binT[idx]], 1u);
            sIdx[p * SPITCH + pos] = (uint16_t)tt;
        }
        __syncthreads();

        // ---- segment accumulation: stream = (p, k-half), warp covers 50 a via float2 ----
        for (int j = 0; j < 4; ++j) {
            const int sid = w + 16 * j;
            if (sid >= 60) break;
            const int p = sid >> 1;
            const int kb = (sid & 1) * 9;
            const uint16_t* sp = sIdx + p * SPITCH;
            const float* aT = ampT + 2 * l;
            #pragma unroll 1
            for (int k = kb; k < kb + 9; ++k) {
                int i = (int)pref[p * 19 + k];
                const int e = (int)pref[p * 19 + k + 1];
                float ax0 = 0.f, ay0 = 0.f, ax1 = 0.f, ay1 = 0.f;
                for (; i + 4 <= e; i += 4) {
                    const uint32_t w0 = *(const uint32_t*)(sp + i);
                    const uint32_t w1 = *(const uint32_t*)(sp + i + 2);
                    if (l < 25) {
                        const float2 v0 = *(const float2*)(aT + (w0 & 0xFFFFu) * APITCH);
                        const float2 v1 = *(const float2*)(aT + (w0 >> 16) * APITCH);
                        const float2 v2 = *(const float2*)(aT + (w1 & 0xFFFFu) * APITCH);
                        const float2 v3 = *(const float2*)(aT + (w1 >> 16) * APITCH);
                        ax0 += v0.x; ay0 += v0.y; ax1 += v1.x; ay1 += v1.y;
                        ax0 += v2.x; ay0 += v2.y; ax1 += v3.x; ay1 += v3.y;
                    }
                }
                if (i + 2 <= e) {
                    const uint32_t w0 = *(const uint32_t*)(sp + i);
                    if (l < 25) {
                        const float2 v0 = *(const float2*)(aT + (w0 & 0xFFFFu) * APITCH);
                        const float2 v1 = *(const float2*)(aT + (w0 >> 16) * APITCH);
                        ax0 += v0.x; ay0 += v0.y; ax1 += v1.x; ay1 += v1.y;
                    }
                }
                if (l < 25) {
                    float2* dp = (float2*)(Dsm + (p * NB + k) * DPITCH + 2 * l);
                    float2 d = *dp;
                    d.x += ax0 + ax1;
                    d.y += ay0 + ay1;
                    *dp = d;
                }
            }
        }
    }
    __syncthreads();

    // ---- epilogue: means -> probs -> entropy -> MI ----
    const float eps = 1e-9f;
    const float LOG18 = 2.8903717578961645f;
    for (int pair = tid; pair < NPAIR; pair += NTHREADS) {
        const int p = pair / 50, a = pair % 50;
        const float* row = Dsm + (size_t)(p * NB) * DPITCH;
        const uint32_t* cnt = cntT + p * NB;
        float m[NB];
        float ss = 0.0f;
        #pragma unroll
        for (int k = 0; k < NB; ++k) {
            const float cf = (float)cnt[k];
            const float mm = row[k * DPITCH + a] / (cf + eps);
            m[k] = mm;
            ss += mm;
        }
        const float inv = 1.0f / (ss + eps);
        float ent = 0.0f;
        #pragma unroll
        for (int k = 0; k < NB; ++k) {
            const float pr = m[k] * inv;
            ent += pr * logf(pr + eps);
        }
        g_mi[(size_t)blockIdx.x * NPAIR + pair] = (LOG18 + ent) * (1.0f / LOG18);
    }
}

__global__ void reduce_kernel(float* __restrict__ out)
{
    const int o = blockIdx.x * 256 + threadIdx.x;
    if (o >= 48000) return;
    const int bc = o / 1500, rem = o % 1500;
    float sum = 0.0f;
    #pragma unroll
    for (int s = 0; s < 20; ++s)
        sum += g_mi[(size_t)(bc * 20 + s) * NPAIR + rem];
    out[o] = sum * 0.05f;
}

extern "C" void kernel_launch(void* const* d_in, const int* in_sizes, int n_in,
                              void* d_out, int out_size)
{
    const float* pha = (const float*)d_in[0];
    const float* amp = (const float*)d_in[1];
    const float* cut = (const float*)d_in[2];
    cudaFuncSetAttribute(mi_sorted, cudaFuncAttributeMaxDynamicSharedMemorySize,
                         SMEM_WORDS * 4);
    mi_sorted<<<NBLOCKS, NTHREADS, SMEM_WORDS * 4>>>(pha, amp, cut);
    reduce_kernel<<<(48000 + 255) / 256, 256>>>((float*)d_out);
}

// round 6
// speedup vs baseline: 1.8300x; 1.4030x over previous
#include <cuda_runtime.h>
#include <stdint.h>
#include <math.h>

#define NTHREADS 1024
#define NB 18
#define NPAIR 1500
#define NBLOCKS 640
#define TC 256
#define NCH 4
#define APITCH 33       // ampT row pitch (u32 words): bank=(t+col)%32, conflict-free both ways
#define DPITCH 52       // Dsm row pitch (s32)
#define SP16 288        // sIdx row pitch (u16), max 256+18 pads

// smem word offsets
#define OFF_DSM  0          // 540*52 = 28080 (s32)
#define OFF_AMPT 28080      // 257*33 = 8481 (u32 = 2 x u16 amps; row 256 = zero pad)
#define OFF_SIDX 36561      // 30*144 = 4320 (u16 30x288)
#define OFF_BINT 40881      // 1920 (u8 30x256)
#define OFF_HIST 42801      // 540
#define OFF_PREF 43341      // 30*19 = 570
#define OFF_OFS  43911      // 540
#define OFF_CNT  44451      // 540
#define OFF_CUT  44991      // 20
#define SMEM_WORDS 45012    // 180,048 bytes

__device__ float g_mi[(size_t)NBLOCKS * NPAIR];

__global__ void __launch_bounds__(NTHREADS, 1)
mi_sorted16(const float* __restrict__ pha, const float* __restrict__ amp,
            const float* __restrict__ cut_g)
{
    extern __shared__ uint32_t smw[];
    int*      Dsm  = (int*)(smw + OFF_DSM);
    uint32_t* ampT = smw + OFF_AMPT;
    uint16_t* sIdx = (uint16_t*)(smw + OFF_SIDX);
    uint8_t*  binT = (uint8_t*)(smw + OFF_BINT);
    uint32_t* hist = smw + OFF_HIST;
    uint32_t* pref = smw + OFF_PREF;
    uint32_t* ofs  = smw + OFF_OFS;
    uint32_t* cnt  = smw + OFF_CNT;
    float*    cut  = (float*)(smw + OFF_CUT);

    const int tid = threadIdx.x;
    const int w = tid >> 5, l = tid & 31;
    const int bc = blockIdx.x / 20, s = blockIdx.x % 20;
    const float* pha_base = pha + ((size_t)bc * 600 + s) * 1024;
    const float* amp_base = amp + ((size_t)bc * 1000 + s) * 1024;

    for (int i = tid; i < 540 * DPITCH; i += NTHREADS) Dsm[i] = 0;
    for (int i = tid; i < 257 * APITCH; i += NTHREADS) ampT[i] = 0u;  // cols 25-31 + pad row stay 0
    for (int i = tid; i < 540; i += NTHREADS) cnt[i] = 0u;
    if (tid < 19) cut[tid] = cut_g[tid];
    __syncthreads();

    const float c0 = cut[0];
    const float invs = 18.0f / (cut[18] - cut[0]);
    const uint32_t ltmask = (1u << l) - 1u;

    for (int c = 0; c < NCH; ++c) {
        const int t0 = c * TC;
        __syncthreads();                       // prev accumulate done (sIdx/ampT/pref reusable)

        // ---- pass A: bins + warp-private histogram (warp w owns p=w) ----
        if (w < 30) {
            if (l < 18) hist[w * 18 + l] = 0u;
            __syncwarp();
            float x[8];
            #pragma unroll
            for (int g = 0; g < 8; ++g)
                x[g] = pha_base[w * 20480 + t0 + g * 32 + l];
            #pragma unroll
            for (int g = 0; g < 8; ++g) {
                const float v = x[g];
                int k = (int)floorf((v - c0) * invs);
                k = k < 0 ? 0 : (k > 17 ? 17 : k);
                k += (k < 17 && cut[k + 1] < v);
                k += (k < 17 && cut[k + 1] < v);
                k -= (k > 0 && !(cut[k] < v));
                k -= (k > 0 && !(cut[k] < v));
                binT[w * 256 + g * 32 + l] = (uint8_t)k;
                const uint32_t m = __match_any_sync(0xFFFFFFFFu, k);
                if ((m & ltmask) == 0u)                      // leader per k
                    hist[w * 18 + k] += (uint32_t)__popc(m); // warp-owned row: no race
            }
        }
        // ---- staging: amp -> u16, ampT[t][col] (coalesced LDG, conflict-free STS) ----
        for (int task = w; task < 400; task += 32) {
            const int a = task >> 3, tb = task & 7;
            const int tt = tb * 32 + l;
            const float v = amp_base[a * 20480 + t0 + tt];
            const uint32_t q = __float2uint_rn(v * 65535.0f);
            ((uint16_t*)ampT)[(tt * APITCH + (a >> 1)) * 2 + (a & 1)] = (uint16_t)q;
        }
        __syncthreads();

        // ---- prefix per p (even-padded segments; pads -> zero row 256) ----
        if (tid < 30) {
            uint32_t run = 0;
            #pragma unroll
            for (int k = 0; k < NB; ++k) {
                const uint32_t h = hist[tid * 18 + k];
                pref[tid * 19 + k] = run;
                ofs[tid * 18 + k] = run;
                cnt[tid * 18 + k] += h;
                if (h & 1u) sIdx[tid * SP16 + run + h] = 256;
                run += (h + 1u) & ~1u;
            }
            pref[tid * 19 + NB] = run;
        }
        __syncthreads();

        // ---- pass B: rank + scatter sorted t-indices (warp w owns p=w) ----
        if (w < 30) {
            #pragma unroll
            for (int g = 0; g < 8; ++g) {
                const int k = (int)binT[w * 256 + g * 32 + l];
                const uint32_t m = __match_any_sync(0xFFFFFFFFu, k);
                const uint32_t rank = (uint32_t)__popc(m & ltmask);
                const uint32_t b = ofs[w * 18 + k];
                sIdx[w * SP16 + b + rank] = (uint16_t)(g * 32 + l);
                if (rank == 0u) ofs[w * 18 + k] = b + (uint32_t)__popc(m);
            }
        }
        __syncthreads();

        // ---- accumulate: seg=(p,k); lanes parallel over a (lane l: a=2l,2l+1) ----
        for (int seg = w; seg < 540; seg += 32) {
            const int p = seg / 18, k = seg - 18 * p;
            const uint32_t* ip = (const uint32_t*)(sIdx + p * SP16);
            const uint32_t* aT = ampT + l;
            int i = (int)(pref[p * 19 + k] >> 1);
            const int e = (int)(pref[p * 19 + k + 1] >> 1);
            int acc0 = 0, acc1 = 0;
            #pragma unroll 2
            for (; i < e; ++i) {
                const uint32_t w2 = ip[i];
                const uint32_t v1 = aT[(w2 & 0xFFFFu) * APITCH];
                const uint32_t v2 = aT[(w2 >> 16) * APITCH];
                acc0 += (int)(v1 & 0xFFFFu) + (int)(v2 & 0xFFFFu);
                acc1 += (int)(v1 >> 16) + (int)(v2 >> 16);
            }
            if (l < 25) {
                int2* dp = (int2*)(Dsm + seg * DPITCH + 2 * l);
                int2 d = *dp;
                d.x += acc0;
                d.y += acc1;
                *dp = d;
            }
        }
    }
    __syncthreads();

    // ---- epilogue: means -> probs -> entropy -> MI ----
    const float eps = 1e-9f;
    const float INVQ = 1.0f / 65535.0f;
    const float LOG18 = 2.8903717578961645f;
    for (int pair = tid; pair < NPAIR; pair += NTHREADS) {
        const int p = pair / 50, a = pair % 50;
        const int* row = Dsm + (size_t)(p * NB) * DPITCH + a;
        const uint32_t* cp = cnt + p * NB;
        float m[NB];
        float ss = 0.0f;
        #pragma unroll
        for (int k = 0; k < NB; ++k) {
            const float Sf = (float)row[k * DPITCH] * INVQ;
            const float mm = Sf / ((float)cp[k] + eps);
            m[k] = mm;
            ss += mm;
        }
        const float inv = 1.0f / (ss + eps);
        float ent = 0.0f;
        #pragma unroll
        for (int k = 0; k < NB; ++k) {
            const float pr = m[k] * inv;
            ent += pr * logf(pr + eps);
        }
        g_mi[(size_t)blockIdx.x * NPAIR + pair] = (LOG18 + ent) * (1.0f / LOG18);
    }
}

__global__ void reduce_kernel(float* __restrict__ out)
{
    const int o = blockIdx.x * 256 + threadIdx.x;
    if (o >= 48000) return;
    const int bc = o / 1500, rem = o % 1500;
    float sum = 0.0f;
    #pragma unroll
    for (int s = 0; s < 20; ++s)
        sum += g_mi[(size_t)(bc * 20 + s) * NPAIR + rem];
    out[o] = sum * 0.05f;
}

// pads shift ncu's "-s 5" so the captured launch is mi_sorted16, not reduce
__global__ void pad_kernel() {}

extern "C" void kernel_launch(void* const* d_in, const int* in_sizes, int n_in,
                              void* d_out, int out_size)
{
    const float* pha = (const float*)d_in[0];
    const float* amp = (const float*)d_in[1];
    const float* cut = (const float*)d_in[2];
    cudaFuncSetAttribute(mi_sorted16, cudaFuncAttributeMaxDynamicSharedMemorySize,
                         SMEM_WORDS * 4);
    mi_sorted16<<<NBLOCKS, NTHREADS, SMEM_WORDS * 4>>>(pha, amp, cut);
    reduce_kernel<<<(48000 + 255) / 256, 256>>>((float*)d_out);
    pad_kernel<<<1, 32>>>();
    pad_kernel<<<1, 32>>>();
    pad_kernel<<<1, 32>>>();
}